// round 15
// baseline (speedup 1.0000x reference)
#include <cuda_runtime.h>
#include <math.h>

#define PI_F 3.14159265358979323846f

// ---------------- scratch arena ----------------
#define OFF_D7    0
#define OFF_D14   100352
#define OFF_D28   501760
#define OFF_C1    2107392
#define OFF_SK1   2308096
#define OFF_C2    2408448
#define OFF_SK2   2809856
#define OFF_C3    3010560
#define OFF_C4    3813376
#define OFF_STATS 5419008
#define ARENA_SZ  5420032

__device__ float g_arena[ARENA_SZ];
__device__ volatile unsigned g_gen = 0;
__device__ unsigned g_count = 0;

// ---------------- software grid barrier (all blocks co-resident by construction) ----------------
__device__ __forceinline__ void grid_barrier() {
    __syncthreads();
    if (threadIdx.x == 0) {
        __threadfence();
        unsigned gen = g_gen;
        if (atomicAdd(&g_count, 1u) == gridDim.x - 1u) {
            g_count = 0u;
            __threadfence();
            g_gen = gen + 1u;
        } else {
            while (g_gen == gen) { __nanosleep(64); }
        }
        __threadfence();
    }
    __syncthreads();
}

// ---------------- fast math ----------------
__device__ __forceinline__ float fast_atan2(float y, float x) {
    float ax = fabsf(x), ay = fabsf(y);
    float mx = fmaxf(fmaxf(ax, ay), 1e-30f);
    float mn = fminf(ax, ay);
    float a = __fdividef(mn, mx);
    float s = a * a;
    float r = fmaf(s, fmaf(s, fmaf(s, fmaf(s, 0.0208351f, -0.085133f),
                                   0.180141f), -0.3302995f), 0.999866f) * a;
    if (ay > ax) r = 1.57079632679f - r;
    if (x < 0.f)  r = 3.14159265359f - r;
    return (y < 0.f) ? -r : r;
}

__device__ __forceinline__ float fast_tanh(float v) {
    float r;
    asm("tanh.approx.f32 %0, %1;" : "=f"(r) : "f"(v));
    return r;
}

// ---------------- reductions ----------------
__device__ __forceinline__ float warp_allreduce(float v) {
    #pragma unroll
    for (int o = 16; o > 0; o >>= 1) v += __shfl_xor_sync(0xffffffffu, v, o);
    return v;
}

__device__ __forceinline__ float block_reduce_sum(float v, float* sh) {
    __syncthreads();
    int lane = threadIdx.x & 31, wid = threadIdx.x >> 5;
    #pragma unroll
    for (int o = 16; o > 0; o >>= 1) v += __shfl_down_sync(0xffffffffu, v, o);
    if (lane == 0) sh[wid] = v;
    __syncthreads();
    float r = 0.f;
    if (threadIdx.x < (blockDim.x >> 5)) r = sh[threadIdx.x];
    if (wid == 0) {
        #pragma unroll
        for (int o = 16; o > 0; o >>= 1) r += __shfl_down_sync(0xffffffffu, r, o);
        if (lane == 0) sh[0] = r;
    }
    __syncthreads();
    return sh[0];
}

// NOTE on SIFT scaling: the reference multiplies mag by g1[yy]*g1[xx]/gsum^2.
// The 1/gsum^2 factor is a UNIFORM scale on the pooled vector and cancels
// exactly in the L2 normalization that follows -> omitted everywhere.

// ---------------- SIFT: block-per-patch (PS=32), GATHER pooling (no atomics) ----------------
// smem layout (floats): patch[1024] | m0a[1024] | m1a[1024] | bo(bytes,256f) | g1[32] | red[32] | part[256]
__device__ void sift7_dev(const float* __restrict__ x, float* __restrict__ desc,
                          int gbid, float* sm) {
    constexpr int PS = 32, STEP = 7;
    constexpr int P = STEP * STEP;
    constexpr int NPIX = PS * PS;
    constexpr int NT = 256;

    float* patch = sm;
    float* m0a   = sm + 1024;
    float* m1a   = sm + 2048;
    unsigned char* boa = (unsigned char*)(sm + 3072);   // 1024 bytes
    float* g1    = sm + 3328;
    float* red   = sm + 3360;
    float* part  = sm + 3392;                            // 256

    const int tid = threadIdx.x;
    const int b   = gbid / P;
    const int off = gbid % P;
    const int ki  = off / STEP, kj = off % STEP;
    const float* xb = x + b * 224 * 224;

    for (int i = tid; i < NPIX; i += NT) {
        int yy = i >> 5, xx = i & 31;
        patch[i] = xb[(yy * STEP + ki) * 224 + xx * STEP + kj];
    }
    if (tid < PS) {
        float d = tid - (PS - 1) * 0.5f;
        g1[tid] = __expf(-(d * d) / (float)(PS * PS));
    }
    __syncthreads();

    // pass 1: per-pixel magnitude split + base bin (plain stores)
    #pragma unroll
    for (int k = 0; k < 4; k++) {
        int i = tid + k * 256;
        int yy = i >> 5, xx = i & 31;
        float xl = patch[yy * PS + (xx > 0      ? xx - 1 : 0)];
        float xr = patch[yy * PS + (xx < PS - 1 ? xx + 1 : PS - 1)];
        float yu = patch[(yy > 0      ? yy - 1 : 0)      * PS + xx];
        float yd = patch[(yy < PS - 1 ? yy + 1 : PS - 1) * PS + xx];
        float gx = 0.5f * (xr - xl);
        float gy = 0.5f * (yd - yu);
        float mag = sqrtf(gx * gx + gy * gy + 1e-10f) * g1[yy] * g1[xx];
        float ori = fast_atan2(gy, gx + 1e-10f) + 2.0f * PI_F;
        float obig = ori * (4.0f / PI_F);
        float b0f = floorf(obig);
        float w1  = obig - b0f;
        int bo0 = ((int)b0f) & 7;
        m0a[i] = (1.f - w1) * mag;
        m1a[i] = w1 * mag;
        boa[i] = (unsigned char)bo0;
    }
    __syncthreads();

    // pass 2: gather per (bin,cell) output; 2 threads split the rows
    {
        const int o    = tid & 127;          // desc index = bin*16 + cell
        const int half = tid >> 7;
        const int bin  = o >> 4;
        const int cell = o & 15;
        const int oy = cell >> 2, ox = cell & 3;
        const int binm1 = (bin + 7) & 7;     // contribution from m1 when bo0 == bin-1
        const int y0 = oy * 8 - 3;
        const int x0 = ox * 8 - 3;
        const int c_lo = (x0 < 0) ? -x0 : 0;
        const int c_hi = (x0 + 12 > 32) ? (32 - x0) : 12;

        float acc = 0.f;
        #pragma unroll
        for (int rr = 0; rr < 6; rr++) {
            int r = rr + half * 6;
            int yy = y0 + r;
            if (yy < 0 || yy >= 32) continue;
            float ty36 = fminf(r + 0.5f, 11.5f - r) * (1.0f / 36.0f);
            int rowb = yy * 32 + x0;
            for (int c = c_lo; c < c_hi; c++) {
                int idx = rowb + c;
                int bb = boa[idx];
                float wgt = ty36 * fminf(c + 0.5f, 11.5f - c);
                if (bb == bin)   acc += m0a[idx] * wgt;
                if (bb == binm1) acc += m1a[idx] * wgt;
            }
        }
        part[tid] = acc;
    }
    __syncthreads();

    float v = 0.f;
    if (tid < 128) v = part[tid] + part[tid + 128];
    float n1 = sqrtf(block_reduce_sum(v * v, red));
    float d1 = v / fmaxf(n1, 1e-12f);
    d1 = fminf(fmaxf(d1, 0.f), 0.2f);
    float n2 = sqrtf(block_reduce_sum(d1 * d1, red));
    float d2 = d1 / fmaxf(n2, 1e-12f);
    float s1 = block_reduce_sum(d2, red);
    if (tid < 128)
        desc[(b * P + off) * 128 + tid] = sqrtf(d2 / fmaxf(s1, 1e-12f) + 1e-10f);
}

// ---------------- SIFT: warp-per-patch (PS=8,16) ----------------
template<int PS, int STEP>
__device__ __forceinline__ void sift_warp_body(const float* __restrict__ x, float* __restrict__ desc,
                                               int pid, int npatch, float* wsm) {
    constexpr int P    = STEP * STEP;
    constexpr int NPIX = PS * PS;
    constexpr int PPL  = NPIX / 32;
    constexpr int BK   = 2 * (PS / 5);
    constexpr int S    = PS / 4;
    constexpr int PAD  = BK / 4;
    constexpr int LOGS = (S == 8) ? 3 : ((S == 4) ? 2 : 1);
    constexpr float HALF   = BK * 0.5f;
    constexpr float INV_H2 = 1.0f / (HALF * HALF);

    if (pid >= npatch) return;
    const int lane = threadIdx.x & 31;
    const int b   = pid / P;
    const int off = pid % P;
    const int ki  = off / STEP, kj = off % STEP;
    const float* xb = x + b * 224 * 224;

    float* patch  = wsm;
    float* pooled = wsm + NPIX;
    float* g1     = wsm + NPIX + 128;

    #pragma unroll
    for (int k = 0; k < PPL; k++) {
        int i = lane + k * 32;
        int yy = i / PS, xx = i % PS;
        patch[i] = xb[(yy * STEP + ki) * 224 + xx * STEP + kj];
    }
    if (lane < PS) {
        float d = lane - (PS - 1) * 0.5f;
        g1[lane] = __expf(-(d * d) / (float)(PS * PS));
    }
    #pragma unroll
    for (int j = 0; j < 4; j++) pooled[lane + j * 32] = 0.f;
    __syncwarp();

    #pragma unroll
    for (int k = 0; k < PPL; k++) {
        int i = lane + k * 32;
        int yy = i / PS, xx = i % PS;
        float xl = patch[yy * PS + (xx > 0      ? xx - 1 : 0)];
        float xr = patch[yy * PS + (xx < PS - 1 ? xx + 1 : PS - 1)];
        float yu = patch[(yy > 0      ? yy - 1 : 0)      * PS + xx];
        float yd = patch[(yy < PS - 1 ? yy + 1 : PS - 1) * PS + xx];
        float gx = 0.5f * (xr - xl);
        float gy = 0.5f * (yd - yu);
        float mag = sqrtf(gx * gx + gy * gy + 1e-10f) * g1[yy] * g1[xx];
        float ori = fast_atan2(gy, gx + 1e-10f) + 2.0f * PI_F;
        float obig = ori * (4.0f / PI_F);
        float b0f = floorf(obig);
        float w1  = obig - b0f;
        int bo0 = ((int)b0f) & 7;
        int bo1 = (bo0 + 1) & 7;
        float m0 = (1.f - w1) * mag, m1 = w1 * mag;
        if (PS == 8) {
            int cb = ((yy >> 1) * 4 + (xx >> 1)) * 8;
            atomicAdd(&pooled[cb + bo0], m0 * 0.25f);
            atomicAdd(&pooled[cb + bo1], m1 * 0.25f);
        } else {
            const int oyh = (yy + PAD) >> LOGS;
            const int oxh = (xx + PAD) >> LOGS;
            #pragma unroll
            for (int t = 0; t < 2; t++) {
                int oy = oyh - t;
                int ry = yy + PAD - oy * S;
                if (oy < 0 || oy > 3 || ry >= BK) continue;
                float ty = HALF - fabsf(ry + 0.5f - HALF);
                #pragma unroll
                for (int s2 = 0; s2 < 2; s2++) {
                    int ox = oxh - s2;
                    int rx = xx + PAD - ox * S;
                    if (ox < 0 || ox > 3 || rx >= BK) continue;
                    float tx = HALF - fabsf(rx + 0.5f - HALF);
                    float wgt = ty * tx * INV_H2;
                    int cb = (oy * 4 + ox) * 8;
                    atomicAdd(&pooled[cb + bo0], m0 * wgt);
                    atomicAdd(&pooled[cb + bo1], m1 * wgt);
                }
            }
        }
    }
    __syncwarp();

    float v[4];
    float p = 0.f;
    #pragma unroll
    for (int j = 0; j < 4; j++) {
        int idx = lane + j * 32;
        v[j] = pooled[(idx & 15) * 8 + (idx >> 4)];
        p += v[j] * v[j];
    }
    float n1 = sqrtf(warp_allreduce(p));
    float inv1 = 1.f / fmaxf(n1, 1e-12f);
    p = 0.f;
    #pragma unroll
    for (int j = 0; j < 4; j++) {
        v[j] = fminf(fmaxf(v[j] * inv1, 0.f), 0.2f);
        p += v[j] * v[j];
    }
    float n2 = sqrtf(warp_allreduce(p));
    float inv2 = 1.f / fmaxf(n2, 1e-12f);
    p = 0.f;
    #pragma unroll
    for (int j = 0; j < 4; j++) { v[j] *= inv2; p += v[j]; }
    float s1 = warp_allreduce(p);
    float invs = 1.f / fmaxf(s1, 1e-12f);
    #pragma unroll
    for (int j = 0; j < 4; j++)
        desc[pid * 128 + lane + j * 32] = sqrtf(v[j] * invs + 1e-10f);
}

// ---------------- ConvTranspose2d tile (k=4,s=2,p=1), ci-chunk staged, 256 threads ----------------
template<int CIN, int C1, int COUT, int COGRP, int HIN, int WIN, int TQ, int CSPLIT, int CSTAGE,
         bool GN_IN, bool DO_STATS, int GIN, int GOUT, int XS>
__device__ void convt_dev(int u, const float* __restrict__ in1, const float* __restrict__ in2,
                          const float* __restrict__ w, const float* __restrict__ bias,
                          const float* __restrict__ gnw, const float* __restrict__ gnb,
                          const float* __restrict__ stats_in, float* __restrict__ stats_out,
                          float* __restrict__ out, float* sm) {
    constexpr int W2 = WIN + 2;
    constexpr int R  = TQ + 2;
    constexpr int PAIRS = (TQ + 1) / 2;
    constexpr int BASE = COGRP * PAIRS * WIN;
    constexpr int ACT  = BASE * CSPLIT;
    constexpr int NT   = 256;
    constexpr int W_ELEMS  = COGRP * CIN * 16;
    constexpr int IN_ELEMS = CSTAGE * R * W2;
    constexpr int CCH    = CSTAGE / CSPLIT;
    constexpr int NROUND = CIN / CSTAGE;
    constexpr int NCG = COUT / COGRP;
    constexpr int CPG_I = GN_IN ? (C1 / GIN) : 1;
    constexpr float CNT_I = (float)(CPG_I * HIN * WIN);
    constexpr int CPG_O = COUT / GOUT;

    float* s_w     = sm;
    float* s_in    = s_w + W_ELEMS;
    float* s_red   = s_in + IN_ELEMS;
    float* s_scale = s_red + ((CSPLIT > 1) ? ACT * 8 : 0);
    float* s_shift = s_scale + (GN_IN ? C1 : 0);
    float* s_stat  = s_shift + (GN_IN ? C1 : 0);

    const int xq = u % XS;
    const int cg = (u / XS) % NCG;
    const int n  = u / (XS * NCG);
    const int qy_base = xq * TQ;
    const int co0 = cg * COGRP;
    const int tid = threadIdx.x;

    __syncthreads(); // smem reuse guard
    if (DO_STATS && tid < 2 * COGRP) s_stat[tid] = 0.f;
    if (GN_IN) {
        for (int c = tid; c < C1; c += NT) {
            int g = c / CPG_I;
            float s  = stats_in[(n * GIN + g) * 2];
            float ss = stats_in[(n * GIN + g) * 2 + 1];
            float m = s / CNT_I;
            float var = ss / CNT_I - m * m;
            float inv = rsqrtf(var + 1e-5f);
            float sc = inv * gnw[c];
            s_scale[c] = sc;
            s_shift[c] = gnb[c] - m * sc;
        }
    }
    for (int e = tid; e < W_ELEMS; e += NT) {
        int k  = e & 15;
        int ci = (e >> 4) % CIN;
        int cl = (e >> 4) / CIN;
        s_w[e] = w[(ci * COUT + co0 + cl) * 16 + k];
    }

    const int base_tid = tid % BASE;
    const int chunk    = tid / BASE;
    const int qx = base_tid % WIN;
    const int pr = (base_tid / WIN) % PAIRS;
    const int cl = base_tid / (WIN * PAIRS);
    const int qyA = qy_base + pr * 2;
    const bool hasB = (pr * 2 + 1) < TQ;
    const int ibase = (pr * 2) * W2 + qx;
    const int HW = HIN * WIN;

    float aA00=0,aA01=0,aA10=0,aA11=0;
    float aB00=0,aB01=0,aB10=0,aB11=0;
    const float* wrow = s_w + cl * CIN * 16;

    for (int rs = 0; rs < NROUND; rs++) {
        __syncthreads();
        for (int e = tid; e < IN_ELEMS; e += NT) {
            int c   = e % W2;
            int r   = (e / W2) % R;
            int cil = e / (W2 * R);
            int ci  = rs * CSTAGE + cil;
            int iy = qy_base - 1 + r;
            int ix = c - 1;
            float v = 0.f;
            if (iy >= 0 && iy < HIN && ix >= 0 && ix < WIN) {
                v = (ci < C1) ? in1[(n * C1 + ci) * HW + iy * WIN + ix]
                              : in2[(n * (CIN - C1) + (ci - C1)) * HW + iy * WIN + ix];
                if (GN_IN && ci < C1)
                    v = fmaxf(fmaf(v, s_scale[ci], s_shift[ci]), 0.f);
            }
            s_in[e] = v;
        }
        __syncthreads();
        if (tid < ACT) {
            #pragma unroll 4
            for (int cc = 0; cc < CCH; cc++) {
                int cil = chunk * CCH + cc;
                int ci  = rs * CSTAGE + cil;
                const float4* wp = (const float4*)(wrow + ci * 16);
                float4 w0 = wp[0], w1 = wp[1], w2 = wp[2], w3 = wp[3];
                const float* ip = s_in + cil * R * W2 + ibase;
                float i00=ip[0], i01=ip[1], i02=ip[2]; ip += W2;
                float i10=ip[0], i11=ip[1], i12=ip[2]; ip += W2;
                float i20=ip[0], i21=ip[1], i22=ip[2]; ip += W2;
                float i30=0.f, i31=0.f, i32=0.f;
                if (hasB) { i30=ip[0]; i31=ip[1]; i32=ip[2]; }
                aA00 += i11*w1.y + i10*w1.w + i01*w3.y + i00*w3.w;
                aA01 += i12*w1.x + i11*w1.z + i02*w3.x + i01*w3.z;
                aA10 += i21*w0.y + i20*w0.w + i11*w2.y + i10*w2.w;
                aA11 += i22*w0.x + i21*w0.z + i12*w2.x + i11*w2.z;
                aB00 += i21*w1.y + i20*w1.w + i11*w3.y + i10*w3.w;
                aB01 += i22*w1.x + i21*w1.z + i12*w3.x + i11*w3.z;
                aB10 += i31*w0.y + i30*w0.w + i21*w2.y + i20*w2.w;
                aB11 += i32*w0.x + i31*w0.z + i22*w2.x + i21*w2.z;
            }
        }
    }

    if (CSPLIT > 1) {
        if (tid < ACT) {
            float* my = s_red + tid * 8;
            my[0]=aA00; my[1]=aA01; my[2]=aA10; my[3]=aA11;
            my[4]=aB00; my[5]=aB01; my[6]=aB10; my[7]=aB11;
        }
        __syncthreads();
        if (tid < ACT && chunk == 0) {
            #pragma unroll
            for (int c = 1; c < CSPLIT; c++) {
                const float* o = s_red + (c * BASE + base_tid) * 8;
                aA00+=o[0]; aA01+=o[1]; aA10+=o[2]; aA11+=o[3];
                aB00+=o[4]; aB01+=o[5]; aB10+=o[6]; aB11+=o[7];
            }
        }
    }

    if (tid < ACT && chunk == 0) {
        const float bb = bias[co0 + cl];
        const int WOUT = 2 * WIN, HOUT = 2 * HIN;
        float* op = out + (((size_t)n * COUT + co0 + cl) * HOUT + 2 * qyA) * WOUT + 2 * qx;
        float v0 = aA00 + bb, v1 = aA01 + bb, v2 = aA10 + bb, v3 = aA11 + bb;
        op[0] = v0; op[1] = v1; op[WOUT] = v2; op[WOUT + 1] = v3;
        float s  = v0 + v1 + v2 + v3;
        float ss = v0*v0 + v1*v1 + v2*v2 + v3*v3;
        if (hasB) {
            op += 2 * WOUT;
            float u0 = aB00 + bb, u1 = aB01 + bb, u2 = aB10 + bb, u3 = aB11 + bb;
            op[0] = u0; op[1] = u1; op[WOUT] = u2; op[WOUT + 1] = u3;
            s  += u0 + u1 + u2 + u3;
            ss += u0*u0 + u1*u1 + u2*u2 + u3*u3;
        }
        if (DO_STATS) {
            atomicAdd(&s_stat[cl * 2],     s);
            atomicAdd(&s_stat[cl * 2 + 1], ss);
        }
    }
    if (DO_STATS) {
        __syncthreads();
        if (tid < COGRP) {
            int g = (co0 + tid) / CPG_O;
            atomicAdd(&stats_out[(n * GOUT + g) * 2],     s_stat[tid * 2]);
            atomicAdd(&stats_out[(n * GOUT + g) * 2 + 1], s_stat[tid * 2 + 1]);
        }
    }
}

__device__ __forceinline__ int reflect224(int i) {
    return i < 0 ? -i : (i >= 224 ? 446 - i : i);
}

// ---------------- fused GN1 + convT5 + jbf + tanh*scale (per 16x16 tile) ----------------
__device__ void jbf_dev(int u, const float* __restrict__ c4, const float* __restrict__ x,
                        const float* __restrict__ fw, const float* __restrict__ fb,
                        const float* __restrict__ g4w, const float* __restrict__ g4b,
                        const float* __restrict__ st4, float* __restrict__ out, float* sm) {
    const int H = 224, W = 224;
    float* s_in = sm;          // 576
    float* s_h0 = sm + 576;    // 400
    float* s_h1 = sm + 976;    // 400
    float* sg   = sm + 1376;   // 400
    float* s_fw = sm + 1776;   // 128

    const int b = u / 196;
    const int rem = u % 196;
    const int tyb = rem / 14, txb = rem % 14;
    const int by = tyb * 16, bx = txb * 16;
    const int tid = threadIdx.x;

    __syncthreads(); // reuse guard
    if (tid < 128) s_fw[tid] = fw[tid];

    float ssum = st4[b * 2], ssq = st4[b * 2 + 1];
    float m = ssum / 50176.f;
    float var = ssq / 50176.f - m * m;
    float inv = rsqrtf(var + 1e-5f);

    const int iy0 = 8 * tyb - 2, ix0 = 8 * txb - 2;
    const float* cb = c4 + (size_t)b * 4 * 112 * 112;
    for (int e = tid; e < 576; e += 256) {
        int ci = e / 144;
        int rr = (e % 144) / 12, cc = e % 12;
        int iy = iy0 + rr, ix = ix0 + cc;
        float v = 0.f;
        if (iy >= 0 && iy < 112 && ix >= 0 && ix < 112) {
            float sc = inv * g4w[ci];
            float sh = g4b[ci] - m * sc;
            v = fmaxf(fmaf(cb[(ci * 112 + iy) * 112 + ix], sc, sh), 0.f);
        }
        s_in[e] = v;
    }
    const float* gx_ = x + (size_t)b * H * W;
    for (int e = tid; e < 400; e += 256) {
        int r = e / 20, c = e % 20;
        sg[e] = gx_[reflect224(by - 2 + r) * W + reflect224(bx - 2 + c)];
    }
    __syncthreads();

    const float fb0 = fb[0], fb1 = fb[1];
    for (int e = tid; e < 400; e += 256) {
        int r = e / 20, c = e % 20;
        int oy = reflect224(by - 2 + r);
        int ox = reflect224(bx - 2 + c);
        int ky0 = (oy + 1) & 1, kx0 = (ox + 1) & 1;
        int iyh = (oy + 1 - ky0) >> 1, ixh = (ox + 1 - kx0) >> 1;
        float a0 = fb0, a1 = fb1;
        #pragma unroll
        for (int dy = 0; dy < 2; dy++) {
            int iy = iyh - dy;
            if (iy < 0 || iy >= 112) continue;
            int il = iy - iy0;
            int kyi = (ky0 + 2 * dy) * 4;
            #pragma unroll
            for (int dx = 0; dx < 2; dx++) {
                int ix = ixh - dx;
                if (ix < 0 || ix >= 112) continue;
                int jl = ix - ix0;
                int k = kyi + kx0 + 2 * dx;
                #pragma unroll
                for (int ci = 0; ci < 4; ci++) {
                    float v = s_in[ci * 144 + il * 12 + jl];
                    a0 = fmaf(v, s_fw[ci * 32 + k], a0);
                    a1 = fmaf(v, s_fw[ci * 32 + 16 + k], a1);
                }
            }
        }
        s_h0[e] = a0; s_h1[e] = a1;
    }
    __syncthreads();

    const int ly = tid / 16, lx = tid % 16;
    const int ci_ = (ly + 2) * 20 + (lx + 2);
    const float gc = sg[ci_];
    const float gs[5] = {0.41111229f, 0.80073740f, 1.0f, 0.80073740f, 0.41111229f};

    float wsum = 0.f, a0 = 0.f, a1 = 0.f;
    #pragma unroll
    for (int dy = 0; dy < 5; dy++) {
        #pragma unroll
        for (int dx = 0; dx < 5; dx++) {
            int si = (ly + dy) * 20 + (lx + dx);
            float d = sg[si] - gc;
            float k = gs[dy] * gs[dx] * __expf(-200.f * d * d);
            wsum += k;
            a0 += k * s_h0[si];
            a1 += k * s_h1[si];
        }
    }
    float invw = 1.f / wsum;
    int oi = (by + ly) * W + (bx + lx);
    out[(size_t)(b * 2 + 0) * H * W + oi] = fast_tanh(a0 * invw) * 0.436f;
    out[(size_t)(b * 2 + 1) * H * W + oi] = fast_tanh(a1 * invw) * 0.615f;
}

// ---------------- parameter pack ----------------
struct Params {
    const float *x;
    const float *d1w, *d1b, *g1w, *g1b, *s1w, *s1b;
    const float *d2w, *d2b, *g2w, *g2b, *s2w, *s2b;
    const float *d3w, *d3b, *g3w, *g3b;
    const float *d4w, *d4b, *g4w, *g4b;
    const float *fw, *fb;
    float *out;
    int B;
};

// ---------------- the mega kernel (4 blocks/SM) ----------------
__global__ void __launch_bounds__(256, 4) mega_kernel(Params p) {
    extern __shared__ float sm[];
    const int tid = threadIdx.x;
    const int G = gridDim.x;
    const int B = p.B;

    float* D7  = g_arena + OFF_D7;
    float* D14 = g_arena + OFF_D14;
    float* D28 = g_arena + OFF_D28;
    float* C1b = g_arena + OFF_C1;
    float* SK1 = g_arena + OFF_SK1;
    float* C2b = g_arena + OFF_C2;
    float* SK2 = g_arena + OFF_SK2;
    float* C3b = g_arena + OFF_C3;
    float* C4b = g_arena + OFF_C4;
    float* ST  = g_arena + OFF_STATS;
    float* ST1 = ST;
    float* ST2 = ST + 256;
    float* ST3 = ST + 384;
    float* ST4 = ST + 448;

    // ---- PHASE 1: all SIFT scales + stats zero (per-unit block sync = smem reuse guard) ----
    {
        const int nA  = B * 49;
        const int n14 = (B * 196 + 7) / 8;
        const int n28 = (B * 784 + 7) / 8;
        const int total = nA + n14 + n28;
        for (int u = blockIdx.x; u < total; u += G) {
            __syncthreads();   // guards smem reuse across unit types
            if (u == 0) {
                for (int i = tid; i < 512; i += 256) ST[i] = 0.f;
            }
            if (u < nA) {
                sift7_dev(p.x, D7, u, sm);
            } else if (u < nA + n14) {
                int wid = tid >> 5;
                int pid = (u - nA) * 8 + wid;
                sift_warp_body<16, 14>(p.x, D14, pid, B * 196, sm + wid * 400);
            } else {
                int wid = tid >> 5;
                int pid = (u - nA - n14) * 8 + wid;
                sift_warp_body<8, 28>(p.x, D28, pid, B * 784, sm + wid * 208);
            }
        }
    }
    grid_barrier();

    // ---- PHASE 2: convT1 tiles (512 units) + skip1 ----
    {
        const int units = B * 32;
        for (int u = blockIdx.x; u < units; u += G)
            convt_dev<128,128,32,1,7,7,7,8,32,false,true,1,8,1>(
                u, D7, D7, p.d1w, p.d1b, nullptr, nullptr, nullptr, ST1, C1b, sm);
        const int t1 = B * 32 * 196;
        for (int idx = blockIdx.x * 256 + tid; idx < t1; idx += G * 256) {
            int s = idx % 196;
            int o = (idx / 196) % 32;
            int n = idx / (196 * 32);
            float acc = p.s1b[o];
            const float* ip = D14 + (size_t)n * 128 * 196 + s;
            const float* wp = p.s1w + o * 128;
            #pragma unroll 8
            for (int c = 0; c < 128; c++) acc += ip[c * 196] * wp[c];
            SK1[idx] = acc;
        }
    }
    grid_barrier();

    // ---- PHASE 3: convT2 (GN8 on C1b + SK1), 512 units + skip2 ----
    {
        const int units = 2 * 16 * B;
        for (int u = blockIdx.x; u < units; u += G)
            convt_dev<64,32,16,1,14,14,7,4,32,true,true,8,4,2>(
                u, C1b, SK1, p.d2w, p.d2b, p.g1w, p.g1b, ST1, ST2, C2b, sm);
        const int t2 = B * 16 * 784;
        for (int idx = blockIdx.x * 256 + tid; idx < t2; idx += G * 256) {
            int s = idx % 784;
            int o = (idx / 784) % 16;
            int n = idx / (784 * 16);
            float acc = p.s2b[o];
            const float* ip = D28 + (size_t)n * 128 * 784 + s;
            const float* wp = p.s2w + o * 128;
            #pragma unroll 8
            for (int c = 0; c < 128; c++) acc += ip[c * 784] * wp[c];
            SK2[idx] = acc;
        }
    }
    grid_barrier();

    // ---- PHASE 4: convT3 (GN4 on C2b + SK2), 512 units ----
    {
        const int units = 4 * 8 * B;
        for (int u = blockIdx.x; u < units; u += G)
            convt_dev<32,16,8,1,28,28,7,2,16,true,true,4,2,4>(
                u, C2b, SK2, p.d3w, p.d3b, p.g2w, p.g2b, ST2, ST3, C3b, sm);
    }
    grid_barrier();

    // ---- PHASE 5: convT4 (GN2 on C3b), 512 units ----
    {
        const int units = 8 * 4 * B;
        for (int u = blockIdx.x; u < units; u += G)
            convt_dev<8,8,4,1,56,56,7,1,8,true,true,2,1,8>(
                u, C3b, C3b, p.d4w, p.d4b, p.g3w, p.g3b, ST3, ST4, C4b, sm);
    }
    grid_barrier();

    // ---- PHASE 6: GN1 + convT5 + joint bilateral + tanh*scale ----
    {
        const int units = 196 * B;
        for (int u = blockIdx.x; u < units; u += G)
            jbf_dev(u, C4b, p.x, p.fw, p.fb, p.g4w, p.g4b, ST4, p.out, sm);
    }
}

// ---------------- launch ----------------
extern "C" void kernel_launch(void* const* d_in, const int* in_sizes, int n_in,
                              void* d_out, int out_size) {
    Params p;
    p.x   = (const float*)d_in[0];
    p.d1w = (const float*)d_in[1];  p.d1b = (const float*)d_in[2];
    p.g1w = (const float*)d_in[3];  p.g1b = (const float*)d_in[4];
    p.s1w = (const float*)d_in[5];  p.s1b = (const float*)d_in[6];
    p.d2w = (const float*)d_in[7];  p.d2b = (const float*)d_in[8];
    p.g2w = (const float*)d_in[9];  p.g2b = (const float*)d_in[10];
    p.s2w = (const float*)d_in[11]; p.s2b = (const float*)d_in[12];
    p.d3w = (const float*)d_in[13]; p.d3b = (const float*)d_in[14];
    p.g3w = (const float*)d_in[15]; p.g3b = (const float*)d_in[16];
    p.d4w = (const float*)d_in[17]; p.d4b = (const float*)d_in[18];
    p.g4w = (const float*)d_in[19]; p.g4b = (const float*)d_in[20];
    p.fw  = (const float*)d_in[21]; p.fb  = (const float*)d_in[22];
    p.out = (float*)d_out;
    p.B   = in_sizes[0] / (224 * 224);

    static int G = 0;
    if (G == 0) {
        int dev = 0, sms = 0;
        cudaGetDevice(&dev);
        cudaDeviceGetAttribute(&sms, cudaDevAttrMultiProcessorCount, dev);
        G = sms * 4;
    }

    mega_kernel<<<G, 256, 30976>>>(p);
}

// round 16
// speedup vs baseline: 1.0686x; 1.0686x over previous
#include <cuda_runtime.h>
#include <math.h>

#define PI_F 3.14159265358979323846f

// ---------------- scratch arena ----------------
#define OFF_D7    0
#define OFF_D14   100352
#define OFF_D28   501760
#define OFF_C1    2107392
#define OFF_SK1   2308096
#define OFF_C2    2408448
#define OFF_SK2   2809856
#define OFF_C3    3010560
#define OFF_C4    3813376
#define OFF_STATS 5419008
#define ARENA_SZ  5420032

__device__ float g_arena[ARENA_SZ];
__device__ volatile unsigned g_gen = 0;
__device__ unsigned g_count = 0;

// ---------------- software grid barrier (all blocks co-resident by construction) ----------------
__device__ __forceinline__ void grid_barrier() {
    __syncthreads();
    if (threadIdx.x == 0) {
        __threadfence();
        unsigned gen = g_gen;
        if (atomicAdd(&g_count, 1u) == gridDim.x - 1u) {
            g_count = 0u;
            __threadfence();
            g_gen = gen + 1u;
        } else {
            while (g_gen == gen) { __nanosleep(64); }
        }
        __threadfence();
    }
    __syncthreads();
}

// ---------------- fast math ----------------
__device__ __forceinline__ float fast_atan2(float y, float x) {
    float ax = fabsf(x), ay = fabsf(y);
    float mx = fmaxf(fmaxf(ax, ay), 1e-30f);
    float mn = fminf(ax, ay);
    float a = __fdividef(mn, mx);
    float s = a * a;
    float r = fmaf(s, fmaf(s, fmaf(s, fmaf(s, 0.0208351f, -0.085133f),
                                   0.180141f), -0.3302995f), 0.999866f) * a;
    if (ay > ax) r = 1.57079632679f - r;
    if (x < 0.f)  r = 3.14159265359f - r;
    return (y < 0.f) ? -r : r;
}

__device__ __forceinline__ float fast_tanh(float v) {
    float r;
    asm("tanh.approx.f32 %0, %1;" : "=f"(r) : "f"(v));
    return r;
}

// ---------------- reductions ----------------
__device__ __forceinline__ float warp_allreduce(float v) {
    #pragma unroll
    for (int o = 16; o > 0; o >>= 1) v += __shfl_xor_sync(0xffffffffu, v, o);
    return v;
}

__device__ __forceinline__ float block_reduce_sum(float v, float* sh) {
    __syncthreads();
    int lane = threadIdx.x & 31, wid = threadIdx.x >> 5;
    #pragma unroll
    for (int o = 16; o > 0; o >>= 1) v += __shfl_down_sync(0xffffffffu, v, o);
    if (lane == 0) sh[wid] = v;
    __syncthreads();
    float r = 0.f;
    if (threadIdx.x < (blockDim.x >> 5)) r = sh[threadIdx.x];
    if (wid == 0) {
        #pragma unroll
        for (int o = 16; o > 0; o >>= 1) r += __shfl_down_sync(0xffffffffu, r, o);
        if (lane == 0) sh[0] = r;
    }
    __syncthreads();
    return sh[0];
}

// NOTE on SIFT scaling: the reference multiplies mag by g1[yy]*g1[xx]/gsum^2.
// The 1/gsum^2 factor is a UNIFORM scale on the pooled vector and cancels
// exactly in the L2 normalization that follows -> omitted everywhere.
// Pool layout: addr = cell*8 + bin (banks spread by bin for spatially-adjacent lanes).

// ---------------- SIFT: block-per-patch (PS=32), 256 threads, per-warp pooled (R14 scatter) ----------------
__device__ void sift7_dev(const float* __restrict__ x, float* __restrict__ desc,
                          int gbid, float* sm) {
    constexpr int PS = 32, STEP = 7;
    constexpr int P = STEP * STEP;
    constexpr int NPIX = PS * PS;
    constexpr int BK = 12, S = 8, PAD = 3;
    constexpr float HALF = 6.0f;
    constexpr float INV_H2 = 1.0f / 36.0f;
    constexpr int NT = 256;

    float* patch  = sm;          // 1024
    float* pooled = sm + 1024;   // 8 warps x 128
    float* g1     = sm + 2048;   // 32
    float* red    = sm + 2080;   // 32

    const int tid = threadIdx.x;
    const int wid = tid >> 5;
    const int b   = gbid / P;
    const int off = gbid % P;
    const int ki  = off / STEP, kj = off % STEP;
    const float* xb = x + b * 224 * 224;

    for (int i = tid; i < NPIX; i += NT) {
        int yy = i >> 5, xx = i & 31;
        patch[i] = xb[(yy * STEP + ki) * 224 + xx * STEP + kj];
    }
    if (tid < PS) {
        float d = tid - (PS - 1) * 0.5f;
        g1[tid] = __expf(-(d * d) / (float)(PS * PS));
    }
    #pragma unroll
    for (int j = 0; j < 4; j++) pooled[tid + j * 256] = 0.f;
    __syncthreads();
    float* mypool = pooled + wid * 128;

    for (int i = tid; i < NPIX; i += NT) {
        int yy = i >> 5, xx = i & 31;
        float xl = patch[yy * PS + (xx > 0      ? xx - 1 : 0)];
        float xr = patch[yy * PS + (xx < PS - 1 ? xx + 1 : PS - 1)];
        float yu = patch[(yy > 0      ? yy - 1 : 0)      * PS + xx];
        float yd = patch[(yy < PS - 1 ? yy + 1 : PS - 1) * PS + xx];
        float gx = 0.5f * (xr - xl);
        float gy = 0.5f * (yd - yu);
        float mag = sqrtf(gx * gx + gy * gy + 1e-10f) * g1[yy] * g1[xx];
        float ori = fast_atan2(gy, gx + 1e-10f) + 2.0f * PI_F;
        float obig = ori * (4.0f / PI_F);
        float b0f = floorf(obig);
        float w1  = obig - b0f;
        int bo0 = ((int)b0f) & 7;
        int bo1 = (bo0 + 1) & 7;
        float m0 = (1.f - w1) * mag, m1 = w1 * mag;
        const int oyh = (yy + PAD) >> 3;
        const int oxh = (xx + PAD) >> 3;
        #pragma unroll
        for (int t = 0; t < 2; t++) {
            int oy = oyh - t;
            int ry = yy + PAD - oy * S;
            if (oy < 0 || oy > 3 || ry >= BK) continue;
            float ty = HALF - fabsf(ry + 0.5f - HALF);
            #pragma unroll
            for (int s2 = 0; s2 < 2; s2++) {
                int ox = oxh - s2;
                int rx = xx + PAD - ox * S;
                if (ox < 0 || ox > 3 || rx >= BK) continue;
                float tx = HALF - fabsf(rx + 0.5f - HALF);
                float wgt = ty * tx * INV_H2;
                int cb = (oy * 4 + ox) * 8;
                atomicAdd(&mypool[cb + bo0], m0 * wgt);
                atomicAdd(&mypool[cb + bo1], m1 * wgt);
            }
        }
    }
    __syncthreads();
    float v = 0.f;
    if (tid < 128) {
        int gaddr = (tid & 15) * 8 + (tid >> 4);  // desc idx bin*16+cell -> stored cell*8+bin
        #pragma unroll
        for (int w = 0; w < 8; w++) v += pooled[w * 128 + gaddr];
    }
    float n1 = sqrtf(block_reduce_sum(v * v, red));
    float d1 = v / fmaxf(n1, 1e-12f);
    d1 = fminf(fmaxf(d1, 0.f), 0.2f);
    float n2 = sqrtf(block_reduce_sum(d1 * d1, red));
    float d2 = d1 / fmaxf(n2, 1e-12f);
    float s1 = block_reduce_sum(d2, red);
    if (tid < 128)
        desc[(b * P + off) * 128 + tid] = sqrtf(d2 / fmaxf(s1, 1e-12f) + 1e-10f);
}

// ---------------- SIFT: warp-per-patch (PS=8,16) ----------------
template<int PS, int STEP>
__device__ __forceinline__ void sift_warp_body(const float* __restrict__ x, float* __restrict__ desc,
                                               int pid, int npatch, float* wsm) {
    constexpr int P    = STEP * STEP;
    constexpr int NPIX = PS * PS;
    constexpr int PPL  = NPIX / 32;
    constexpr int BK   = 2 * (PS / 5);
    constexpr int S    = PS / 4;
    constexpr int PAD  = BK / 4;
    constexpr int LOGS = (S == 8) ? 3 : ((S == 4) ? 2 : 1);
    constexpr float HALF   = BK * 0.5f;
    constexpr float INV_H2 = 1.0f / (HALF * HALF);

    if (pid >= npatch) return;
    const int lane = threadIdx.x & 31;
    const int b   = pid / P;
    const int off = pid % P;
    const int ki  = off / STEP, kj = off % STEP;
    const float* xb = x + b * 224 * 224;

    float* patch  = wsm;
    float* pooled = wsm + NPIX;
    float* g1     = wsm + NPIX + 128;

    #pragma unroll
    for (int k = 0; k < PPL; k++) {
        int i = lane + k * 32;
        int yy = i / PS, xx = i % PS;
        patch[i] = xb[(yy * STEP + ki) * 224 + xx * STEP + kj];
    }
    if (lane < PS) {
        float d = lane - (PS - 1) * 0.5f;
        g1[lane] = __expf(-(d * d) / (float)(PS * PS));
    }
    #pragma unroll
    for (int j = 0; j < 4; j++) pooled[lane + j * 32] = 0.f;
    __syncwarp();

    #pragma unroll
    for (int k = 0; k < PPL; k++) {
        int i = lane + k * 32;
        int yy = i / PS, xx = i % PS;
        float xl = patch[yy * PS + (xx > 0      ? xx - 1 : 0)];
        float xr = patch[yy * PS + (xx < PS - 1 ? xx + 1 : PS - 1)];
        float yu = patch[(yy > 0      ? yy - 1 : 0)      * PS + xx];
        float yd = patch[(yy < PS - 1 ? yy + 1 : PS - 1) * PS + xx];
        float gx = 0.5f * (xr - xl);
        float gy = 0.5f * (yd - yu);
        float mag = sqrtf(gx * gx + gy * gy + 1e-10f) * g1[yy] * g1[xx];
        float ori = fast_atan2(gy, gx + 1e-10f) + 2.0f * PI_F;
        float obig = ori * (4.0f / PI_F);
        float b0f = floorf(obig);
        float w1  = obig - b0f;
        int bo0 = ((int)b0f) & 7;
        int bo1 = (bo0 + 1) & 7;
        float m0 = (1.f - w1) * mag, m1 = w1 * mag;
        if (PS == 8) {
            int cb = ((yy >> 1) * 4 + (xx >> 1)) * 8;
            atomicAdd(&pooled[cb + bo0], m0 * 0.25f);
            atomicAdd(&pooled[cb + bo1], m1 * 0.25f);
        } else {
            const int oyh = (yy + PAD) >> LOGS;
            const int oxh = (xx + PAD) >> LOGS;
            #pragma unroll
            for (int t = 0; t < 2; t++) {
                int oy = oyh - t;
                int ry = yy + PAD - oy * S;
                if (oy < 0 || oy > 3 || ry >= BK) continue;
                float ty = HALF - fabsf(ry + 0.5f - HALF);
                #pragma unroll
                for (int s2 = 0; s2 < 2; s2++) {
                    int ox = oxh - s2;
                    int rx = xx + PAD - ox * S;
                    if (ox < 0 || ox > 3 || rx >= BK) continue;
                    float tx = HALF - fabsf(rx + 0.5f - HALF);
                    float wgt = ty * tx * INV_H2;
                    int cb = (oy * 4 + ox) * 8;
                    atomicAdd(&pooled[cb + bo0], m0 * wgt);
                    atomicAdd(&pooled[cb + bo1], m1 * wgt);
                }
            }
        }
    }
    __syncwarp();

    float v[4];
    float p = 0.f;
    #pragma unroll
    for (int j = 0; j < 4; j++) {
        int idx = lane + j * 32;
        v[j] = pooled[(idx & 15) * 8 + (idx >> 4)];
        p += v[j] * v[j];
    }
    float n1 = sqrtf(warp_allreduce(p));
    float inv1 = 1.f / fmaxf(n1, 1e-12f);
    p = 0.f;
    #pragma unroll
    for (int j = 0; j < 4; j++) {
        v[j] = fminf(fmaxf(v[j] * inv1, 0.f), 0.2f);
        p += v[j] * v[j];
    }
    float n2 = sqrtf(warp_allreduce(p));
    float inv2 = 1.f / fmaxf(n2, 1e-12f);
    p = 0.f;
    #pragma unroll
    for (int j = 0; j < 4; j++) { v[j] *= inv2; p += v[j]; }
    float s1 = warp_allreduce(p);
    float invs = 1.f / fmaxf(s1, 1e-12f);
    #pragma unroll
    for (int j = 0; j < 4; j++)
        desc[pid * 128 + lane + j * 32] = sqrtf(v[j] * invs + 1e-10f);
}

// ---------------- ConvTranspose2d tile (k=4,s=2,p=1), ci-chunk staged, 256 threads ----------------
template<int CIN, int C1, int COUT, int COGRP, int HIN, int WIN, int TQ, int CSPLIT, int CSTAGE,
         bool GN_IN, bool DO_STATS, int GIN, int GOUT, int XS>
__device__ void convt_dev(int u, const float* __restrict__ in1, const float* __restrict__ in2,
                          const float* __restrict__ w, const float* __restrict__ bias,
                          const float* __restrict__ gnw, const float* __restrict__ gnb,
                          const float* __restrict__ stats_in, float* __restrict__ stats_out,
                          float* __restrict__ out, float* sm) {
    constexpr int W2 = WIN + 2;
    constexpr int R  = TQ + 2;
    constexpr int PAIRS = (TQ + 1) / 2;
    constexpr int BASE = COGRP * PAIRS * WIN;
    constexpr int ACT  = BASE * CSPLIT;
    constexpr int NT   = 256;
    constexpr int W_ELEMS  = COGRP * CIN * 16;
    constexpr int IN_ELEMS = CSTAGE * R * W2;
    constexpr int CCH    = CSTAGE / CSPLIT;
    constexpr int NROUND = CIN / CSTAGE;
    constexpr int NCG = COUT / COGRP;
    constexpr int CPG_I = GN_IN ? (C1 / GIN) : 1;
    constexpr float CNT_I = (float)(CPG_I * HIN * WIN);
    constexpr int CPG_O = COUT / GOUT;

    float* s_w     = sm;
    float* s_in    = s_w + W_ELEMS;
    float* s_red   = s_in + IN_ELEMS;
    float* s_scale = s_red + ((CSPLIT > 1) ? ACT * 8 : 0);
    float* s_shift = s_scale + (GN_IN ? C1 : 0);
    float* s_stat  = s_shift + (GN_IN ? C1 : 0);

    const int xq = u % XS;
    const int cg = (u / XS) % NCG;
    const int n  = u / (XS * NCG);
    const int qy_base = xq * TQ;
    const int co0 = cg * COGRP;
    const int tid = threadIdx.x;

    __syncthreads(); // smem reuse guard
    if (DO_STATS && tid < 2 * COGRP) s_stat[tid] = 0.f;
    if (GN_IN) {
        for (int c = tid; c < C1; c += NT) {
            int g = c / CPG_I;
            float s  = stats_in[(n * GIN + g) * 2];
            float ss = stats_in[(n * GIN + g) * 2 + 1];
            float m = s / CNT_I;
            float var = ss / CNT_I - m * m;
            float inv = rsqrtf(var + 1e-5f);
            float sc = inv * gnw[c];
            s_scale[c] = sc;
            s_shift[c] = gnb[c] - m * sc;
        }
    }
    for (int e = tid; e < W_ELEMS; e += NT) {
        int k  = e & 15;
        int ci = (e >> 4) % CIN;
        int cl = (e >> 4) / CIN;
        s_w[e] = w[(ci * COUT + co0 + cl) * 16 + k];
    }

    const int base_tid = tid % BASE;
    const int chunk    = tid / BASE;
    const int qx = base_tid % WIN;
    const int pr = (base_tid / WIN) % PAIRS;
    const int cl = base_tid / (WIN * PAIRS);
    const int qyA = qy_base + pr * 2;
    const bool hasB = (pr * 2 + 1) < TQ;
    const int ibase = (pr * 2) * W2 + qx;
    const int HW = HIN * WIN;

    float aA00=0,aA01=0,aA10=0,aA11=0;
    float aB00=0,aB01=0,aB10=0,aB11=0;
    const float* wrow = s_w + cl * CIN * 16;

    for (int rs = 0; rs < NROUND; rs++) {
        __syncthreads();
        for (int e = tid; e < IN_ELEMS; e += NT) {
            int c   = e % W2;
            int r   = (e / W2) % R;
            int cil = e / (W2 * R);
            int ci  = rs * CSTAGE + cil;
            int iy = qy_base - 1 + r;
            int ix = c - 1;
            float v = 0.f;
            if (iy >= 0 && iy < HIN && ix >= 0 && ix < WIN) {
                v = (ci < C1) ? in1[(n * C1 + ci) * HW + iy * WIN + ix]
                              : in2[(n * (CIN - C1) + (ci - C1)) * HW + iy * WIN + ix];
                if (GN_IN && ci < C1)
                    v = fmaxf(fmaf(v, s_scale[ci], s_shift[ci]), 0.f);
            }
            s_in[e] = v;
        }
        __syncthreads();
        if (tid < ACT) {
            #pragma unroll 4
            for (int cc = 0; cc < CCH; cc++) {
                int cil = chunk * CCH + cc;
                int ci  = rs * CSTAGE + cil;
                const float4* wp = (const float4*)(wrow + ci * 16);
                float4 w0 = wp[0], w1 = wp[1], w2 = wp[2], w3 = wp[3];
                const float* ip = s_in + cil * R * W2 + ibase;
                float i00=ip[0], i01=ip[1], i02=ip[2]; ip += W2;
                float i10=ip[0], i11=ip[1], i12=ip[2]; ip += W2;
                float i20=ip[0], i21=ip[1], i22=ip[2]; ip += W2;
                float i30=0.f, i31=0.f, i32=0.f;
                if (hasB) { i30=ip[0]; i31=ip[1]; i32=ip[2]; }
                aA00 += i11*w1.y + i10*w1.w + i01*w3.y + i00*w3.w;
                aA01 += i12*w1.x + i11*w1.z + i02*w3.x + i01*w3.z;
                aA10 += i21*w0.y + i20*w0.w + i11*w2.y + i10*w2.w;
                aA11 += i22*w0.x + i21*w0.z + i12*w2.x + i11*w2.z;
                aB00 += i21*w1.y + i20*w1.w + i11*w3.y + i10*w3.w;
                aB01 += i22*w1.x + i21*w1.z + i12*w3.x + i11*w3.z;
                aB10 += i31*w0.y + i30*w0.w + i21*w2.y + i20*w2.w;
                aB11 += i32*w0.x + i31*w0.z + i22*w2.x + i21*w2.z;
            }
        }
    }

    if (CSPLIT > 1) {
        if (tid < ACT) {
            float* my = s_red + tid * 8;
            my[0]=aA00; my[1]=aA01; my[2]=aA10; my[3]=aA11;
            my[4]=aB00; my[5]=aB01; my[6]=aB10; my[7]=aB11;
        }
        __syncthreads();
        if (tid < ACT && chunk == 0) {
            #pragma unroll
            for (int c = 1; c < CSPLIT; c++) {
                const float* o = s_red + (c * BASE + base_tid) * 8;
                aA00+=o[0]; aA01+=o[1]; aA10+=o[2]; aA11+=o[3];
                aB00+=o[4]; aB01+=o[5]; aB10+=o[6]; aB11+=o[7];
            }
        }
    }

    if (tid < ACT && chunk == 0) {
        const float bb = bias[co0 + cl];
        const int WOUT = 2 * WIN, HOUT = 2 * HIN;
        float* op = out + (((size_t)n * COUT + co0 + cl) * HOUT + 2 * qyA) * WOUT + 2 * qx;
        float v0 = aA00 + bb, v1 = aA01 + bb, v2 = aA10 + bb, v3 = aA11 + bb;
        op[0] = v0; op[1] = v1; op[WOUT] = v2; op[WOUT + 1] = v3;
        float s  = v0 + v1 + v2 + v3;
        float ss = v0*v0 + v1*v1 + v2*v2 + v3*v3;
        if (hasB) {
            op += 2 * WOUT;
            float u0 = aB00 + bb, u1 = aB01 + bb, u2 = aB10 + bb, u3 = aB11 + bb;
            op[0] = u0; op[1] = u1; op[WOUT] = u2; op[WOUT + 1] = u3;
            s  += u0 + u1 + u2 + u3;
            ss += u0*u0 + u1*u1 + u2*u2 + u3*u3;
        }
        if (DO_STATS) {
            atomicAdd(&s_stat[cl * 2],     s);
            atomicAdd(&s_stat[cl * 2 + 1], ss);
        }
    }
    if (DO_STATS) {
        __syncthreads();
        if (tid < COGRP) {
            int g = (co0 + tid) / CPG_O;
            atomicAdd(&stats_out[(n * GOUT + g) * 2],     s_stat[tid * 2]);
            atomicAdd(&stats_out[(n * GOUT + g) * 2 + 1], s_stat[tid * 2 + 1]);
        }
    }
}

__device__ __forceinline__ int reflect224(int i) {
    return i < 0 ? -i : (i >= 224 ? 446 - i : i);
}

// ---------------- fused GN1 + convT5 + jbf + tanh*scale (per 16x32 tile) ----------------
// smem: s_in[960] | s_h0[720] | s_h1[720] | sg[720] | s_fw[128]  = 3248 floats (13KB)
__device__ void jbf_dev(int u, const float* __restrict__ c4, const float* __restrict__ x,
                        const float* __restrict__ fw, const float* __restrict__ fb,
                        const float* __restrict__ g4w, const float* __restrict__ g4b,
                        const float* __restrict__ st4, float* __restrict__ out, float* sm) {
    const int H = 224, W = 224;
    float* s_in = sm;          // 4 x 12 x 20 = 960
    float* s_h0 = sm + 960;    // 20 x 36 = 720
    float* s_h1 = sm + 1680;   // 720
    float* sg   = sm + 2400;   // 720
    float* s_fw = sm + 3120;   // 128

    const int b = u / 98;
    const int rem = u % 98;
    const int tyb = rem / 7, txb = rem % 7;    // 14 y-tiles x 7 x-tiles
    const int by = tyb * 16, bx = txb * 32;
    const int tid = threadIdx.x;

    __syncthreads(); // reuse guard
    if (tid < 128) s_fw[tid] = fw[tid];

    float ssum = st4[b * 2], ssq = st4[b * 2 + 1];
    float m = ssum / 50176.f;
    float var = ssq / 50176.f - m * m;
    float inv = rsqrtf(var + 1e-5f);

    const int iy0 = 8 * tyb - 2, ix0 = 16 * txb - 2;
    const float* cb = c4 + (size_t)b * 4 * 112 * 112;
    for (int e = tid; e < 960; e += 256) {
        int ci = e / 240;
        int rr = (e % 240) / 20, cc = e % 20;
        int iy = iy0 + rr, ix = ix0 + cc;
        float v = 0.f;
        if (iy >= 0 && iy < 112 && ix >= 0 && ix < 112) {
            float sc = inv * g4w[ci];
            float sh = g4b[ci] - m * sc;
            v = fmaxf(fmaf(cb[(ci * 112 + iy) * 112 + ix], sc, sh), 0.f);
        }
        s_in[e] = v;
    }
    const float* gx_ = x + (size_t)b * H * W;
    for (int e = tid; e < 720; e += 256) {
        int r = e / 36, c = e % 36;
        sg[e] = gx_[reflect224(by - 2 + r) * W + reflect224(bx - 2 + c)];
    }
    __syncthreads();

    const float fb0 = fb[0], fb1 = fb[1];
    for (int e = tid; e < 720; e += 256) {
        int r = e / 36, c = e % 36;
        int oy = reflect224(by - 2 + r);
        int ox = reflect224(bx - 2 + c);
        int ky0 = (oy + 1) & 1, kx0 = (ox + 1) & 1;
        int iyh = (oy + 1 - ky0) >> 1, ixh = (ox + 1 - kx0) >> 1;
        float a0 = fb0, a1 = fb1;
        #pragma unroll
        for (int dy = 0; dy < 2; dy++) {
            int iy = iyh - dy;
            if (iy < 0 || iy >= 112) continue;
            int il = iy - iy0;
            int kyi = (ky0 + 2 * dy) * 4;
            #pragma unroll
            for (int dx = 0; dx < 2; dx++) {
                int ix = ixh - dx;
                if (ix < 0 || ix >= 112) continue;
                int jl = ix - ix0;
                int k = kyi + kx0 + 2 * dx;
                #pragma unroll
                for (int ci = 0; ci < 4; ci++) {
                    float v = s_in[ci * 240 + il * 20 + jl];
                    a0 = fmaf(v, s_fw[ci * 32 + k], a0);
                    a1 = fmaf(v, s_fw[ci * 32 + 16 + k], a1);
                }
            }
        }
        s_h0[e] = a0; s_h1[e] = a1;
    }
    __syncthreads();

    const float gs[5] = {0.41111229f, 0.80073740f, 1.0f, 0.80073740f, 0.41111229f};
    #pragma unroll
    for (int h = 0; h < 2; h++) {
        int idx = tid + h * 256;
        int row = idx >> 5, col = idx & 31;
        int ci_ = (row + 2) * 36 + (col + 2);
        float gc = sg[ci_];
        float wsum = 0.f, a0 = 0.f, a1 = 0.f;
        #pragma unroll
        for (int dy = 0; dy < 5; dy++) {
            #pragma unroll
            for (int dx = 0; dx < 5; dx++) {
                int si = (row + dy) * 36 + (col + dx);
                float d = sg[si] - gc;
                float k = gs[dy] * gs[dx] * __expf(-200.f * d * d);
                wsum += k;
                a0 += k * s_h0[si];
                a1 += k * s_h1[si];
            }
        }
        float invw = 1.f / wsum;
        int oi = (by + row) * W + (bx + col);
        out[(size_t)(b * 2 + 0) * H * W + oi] = fast_tanh(a0 * invw) * 0.436f;
        out[(size_t)(b * 2 + 1) * H * W + oi] = fast_tanh(a1 * invw) * 0.615f;
    }
}

// ---------------- parameter pack ----------------
struct Params {
    const float *x;
    const float *d1w, *d1b, *g1w, *g1b, *s1w, *s1b;
    const float *d2w, *d2b, *g2w, *g2b, *s2w, *s2b;
    const float *d3w, *d3b, *g3w, *g3b;
    const float *d4w, *d4b, *g4w, *g4b;
    const float *fw, *fb;
    float *out;
    int B;
};

// ---------------- the mega kernel (4 blocks/SM) ----------------
__global__ void __launch_bounds__(256, 4) mega_kernel(Params p) {
    extern __shared__ float sm[];
    const int tid = threadIdx.x;
    const int G = gridDim.x;
    const int B = p.B;

    float* D7  = g_arena + OFF_D7;
    float* D14 = g_arena + OFF_D14;
    float* D28 = g_arena + OFF_D28;
    float* C1b = g_arena + OFF_C1;
    float* SK1 = g_arena + OFF_SK1;
    float* C2b = g_arena + OFF_C2;
    float* SK2 = g_arena + OFF_SK2;
    float* C3b = g_arena + OFF_C3;
    float* C4b = g_arena + OFF_C4;
    float* ST  = g_arena + OFF_STATS;
    float* ST1 = ST;
    float* ST2 = ST + 256;
    float* ST3 = ST + 384;
    float* ST4 = ST + 448;

    // ---- PHASE 1: all SIFT scales + stats zero (per-unit block sync = smem reuse guard) ----
    {
        const int nA  = B * 49;
        const int n14 = (B * 196 + 7) / 8;
        const int n28 = (B * 784 + 7) / 8;
        const int total = nA + n14 + n28;
        for (int u = blockIdx.x; u < total; u += G) {
            __syncthreads();   // guards smem reuse across unit types
            if (u == 0) {
                for (int i = tid; i < 512; i += 256) ST[i] = 0.f;
            }
            if (u < nA) {
                sift7_dev(p.x, D7, u, sm);
            } else if (u < nA + n14) {
                int wid = tid >> 5;
                int pid = (u - nA) * 8 + wid;
                sift_warp_body<16, 14>(p.x, D14, pid, B * 196, sm + wid * 400);
            } else {
                int wid = tid >> 5;
                int pid = (u - nA - n14) * 8 + wid;
                sift_warp_body<8, 28>(p.x, D28, pid, B * 784, sm + wid * 208);
            }
        }
    }
    grid_barrier();

    // ---- PHASE 2: convT1 tiles (512 units) + skip1 ----
    {
        const int units = B * 32;
        for (int u = blockIdx.x; u < units; u += G)
            convt_dev<128,128,32,1,7,7,7,8,32,false,true,1,8,1>(
                u, D7, D7, p.d1w, p.d1b, nullptr, nullptr, nullptr, ST1, C1b, sm);
        const int t1 = B * 32 * 196;
        for (int idx = blockIdx.x * 256 + tid; idx < t1; idx += G * 256) {
            int s = idx % 196;
            int o = (idx / 196) % 32;
            int n = idx / (196 * 32);
            float acc = p.s1b[o];
            const float* ip = D14 + (size_t)n * 128 * 196 + s;
            const float* wp = p.s1w + o * 128;
            #pragma unroll 8
            for (int c = 0; c < 128; c++) acc += ip[c * 196] * wp[c];
            SK1[idx] = acc;
        }
    }
    grid_barrier();

    // ---- PHASE 3: convT2 (GN8 on C1b + SK1), 512 units + skip2 ----
    {
        const int units = 2 * 16 * B;
        for (int u = blockIdx.x; u < units; u += G)
            convt_dev<64,32,16,1,14,14,7,4,32,true,true,8,4,2>(
                u, C1b, SK1, p.d2w, p.d2b, p.g1w, p.g1b, ST1, ST2, C2b, sm);
        const int t2 = B * 16 * 784;
        for (int idx = blockIdx.x * 256 + tid; idx < t2; idx += G * 256) {
            int s = idx % 784;
            int o = (idx / 784) % 16;
            int n = idx / (784 * 16);
            float acc = p.s2b[o];
            const float* ip = D28 + (size_t)n * 128 * 784 + s;
            const float* wp = p.s2w + o * 128;
            #pragma unroll 8
            for (int c = 0; c < 128; c++) acc += ip[c * 784] * wp[c];
            SK2[idx] = acc;
        }
    }
    grid_barrier();

    // ---- PHASE 4: convT3 (GN4 on C2b + SK2), 512 units ----
    {
        const int units = 4 * 8 * B;
        for (int u = blockIdx.x; u < units; u += G)
            convt_dev<32,16,8,1,28,28,7,2,16,true,true,4,2,4>(
                u, C2b, SK2, p.d3w, p.d3b, p.g2w, p.g2b, ST2, ST3, C3b, sm);
    }
    grid_barrier();

    // ---- PHASE 5: convT4 (GN2 on C3b), 512 units ----
    {
        const int units = 8 * 4 * B;
        for (int u = blockIdx.x; u < units; u += G)
            convt_dev<8,8,4,1,56,56,7,1,8,true,true,2,1,8>(
                u, C3b, C3b, p.d4w, p.d4b, p.g3w, p.g3b, ST3, ST4, C4b, sm);
    }
    grid_barrier();

    // ---- PHASE 6: GN1 + convT5 + joint bilateral + tanh*scale (16x32 tiles) ----
    {
        const int units = 98 * B;
        for (int u = blockIdx.x; u < units; u += G)
            jbf_dev(u, C4b, p.x, p.fw, p.fb, p.g4w, p.g4b, ST4, p.out, sm);
    }
}

// ---------------- launch ----------------
extern "C" void kernel_launch(void* const* d_in, const int* in_sizes, int n_in,
                              void* d_out, int out_size) {
    Params p;
    p.x   = (const float*)d_in[0];
    p.d1w = (const float*)d_in[1];  p.d1b = (const float*)d_in[2];
    p.g1w = (const float*)d_in[3];  p.g1b = (const float*)d_in[4];
    p.s1w = (const float*)d_in[5];  p.s1b = (const float*)d_in[6];
    p.d2w = (const float*)d_in[7];  p.d2b = (const float*)d_in[8];
    p.g2w = (const float*)d_in[9];  p.g2b = (const float*)d_in[10];
    p.s2w = (const float*)d_in[11]; p.s2b = (const float*)d_in[12];
    p.d3w = (const float*)d_in[13]; p.d3b = (const float*)d_in[14];
    p.g3w = (const float*)d_in[15]; p.g3b = (const float*)d_in[16];
    p.d4w = (const float*)d_in[17]; p.d4b = (const float*)d_in[18];
    p.g4w = (const float*)d_in[19]; p.g4b = (const float*)d_in[20];
    p.fw  = (const float*)d_in[21]; p.fb  = (const float*)d_in[22];
    p.out = (float*)d_out;
    p.B   = in_sizes[0] / (224 * 224);

    static int G = 0;
    if (G == 0) {
        int dev = 0, sms = 0;
        cudaGetDevice(&dev);
        cudaDeviceGetAttribute(&sms, cudaDevAttrMultiProcessorCount, dev);
        G = sms * 4;
    }

    mega_kernel<<<G, 256, 30976>>>(p);
}